// round 13
// baseline (speedup 1.0000x reference)
#include <cuda_runtime.h>
#include <cuda_fp16.h>
#include <cstdint>

#define BSZ 1024
#define GF 512
#define IFT 512
#define OFT 512
#define NL 64
#define GC 63
#define KMAIN (IFT * NL)          // 32768
#define KTOT (KMAIN + NL)         // 32832
#define KT2   32896               // padded to 257 chunks of 128
#define KSPLIT 4
#define TILE_M 128
#define TILE_N 128
#define NTHR 640                  // 16 consumer warps + 4 producer warps
#define NBUF 3

// ---------------------------------------------------------------------------
// static device scratch
// ---------------------------------------------------------------------------
__device__ __align__(256) float  g_leafp[BSZ * NL];                  // 256KB
__device__ __align__(256) float  g_xT[IFT * BSZ];                    // 2MB
__device__ __align__(256) __half g_pwh[(size_t)OFT * KT2];           // 33.7MB fp16 B

// ---------------------------------------------------------------------------
// smem layout: 3 fp16 tile-sets (A|B), 256B rows (K-chunk = 128 fp16)
// ---------------------------------------------------------------------------
#define ROWB 272                    // fp16 tile row stride (128*2 + 16 pad)
#define TILEB (128 * ROWB)          // 34816
#define SETSZ (2 * TILEB)           // A | B = 69632
#define OFF_A 0
#define OFF_B TILEB
#define SMEM_SZ (NBUF * SETSZ)      // 208896

// named barriers: full[0..2] = 1..3, empty[0..2] = 4..6
#define BARF(b) (1 + (b))
#define BARE(b) (4 + (b))
#define BAR_SYNC(id)   asm volatile("bar.sync %0, %1;"   :: "r"(id), "r"(NTHR) : "memory")
#define BAR_ARRIVE(id) asm volatile("bar.arrive %0, %1;" :: "r"(id), "r"(NTHR) : "memory")

// ---------------------------------------------------------------------------
// PTX helpers (base sm_103 target only — no 'a'-gated instructions)
// ---------------------------------------------------------------------------
__device__ __forceinline__ uint32_t smem_u32(const void* p) {
    uint32_t a;
    asm("{ .reg .u64 t; cvta.to.shared.u64 t, %1; cvt.u32.u64 %0, t; }" : "=r"(a) : "l"(p));
    return a;
}
#define CPA16(dst, src) \
    asm volatile("cp.async.cg.shared.global [%0], [%1], 16;" :: "r"(dst), "l"(src) : "memory")
#define CPCOMMIT() asm volatile("cp.async.commit_group;" ::: "memory")
#define CPWAIT1()  asm volatile("cp.async.wait_group 1;" ::: "memory")
#define CPWAIT0()  asm volatile("cp.async.wait_group 0;" ::: "memory")

__device__ __forceinline__ void ldsm4(uint32_t (&r)[4], uint32_t a) {
    asm volatile("ldmatrix.sync.aligned.m8n8.x4.shared.b16 {%0,%1,%2,%3}, [%4];"
        : "=r"(r[0]), "=r"(r[1]), "=r"(r[2]), "=r"(r[3]) : "r"(a));
}
__device__ __forceinline__ void mma16816(float* d, const uint32_t* a, const uint32_t* b) {
    asm volatile("mma.sync.aligned.m16n8k16.row.col.f32.f16.f16.f32 "
        "{%0,%1,%2,%3}, {%4,%5,%6,%7}, {%8,%9}, {%0,%1,%2,%3};"
        : "+f"(d[0]), "+f"(d[1]), "+f"(d[2]), "+f"(d[3])
        : "r"(a[0]), "r"(a[1]), "r"(a[2]), "r"(a[3]), "r"(b[0]), "r"(b[1]));
}
__device__ __forceinline__ uint32_t hbits2(__half2 h) {
    return *reinterpret_cast<uint32_t*>(&h);
}
__device__ __forceinline__ void pack8_store(const float* v, char* dst) {
    __half2 h0 = __floats2half2_rn(v[0], v[1]);
    __half2 h1 = __floats2half2_rn(v[2], v[3]);
    __half2 h2 = __floats2half2_rn(v[4], v[5]);
    __half2 h3 = __floats2half2_rn(v[6], v[7]);
    *reinterpret_cast<uint4*>(dst) = make_uint4(hbits2(h0), hbits2(h1), hbits2(h2), hbits2(h3));
}

// ---------------------------------------------------------------------------
// Kernel 1 (fused prep), 256 threads/block:
//   [0, 1024)      : gating+tree -> g_leafp
//   [1024, 1536)   : x transpose -> g_xT (512 tiles)
//   [1536, 9728)   : pw fp32 -> fp16 (8192 blocks)
//   [9728, 9744)   : pb fp32 -> fp16 (16 blocks)
//   [9744, 9760)   : zero pad region [32832, 32896) (16 blocks)
//   [9760, 10272)  : zero out (512 blocks x 4KB)
// ---------------------------------------------------------------------------
__global__ void prep_kernel(const float* __restrict__ xg,
                            const float* __restrict__ gw,
                            const float* __restrict__ gb,
                            const float* __restrict__ xl,
                            const float* __restrict__ pw,
                            const float* __restrict__ pb,
                            float* __restrict__ out) {
    const unsigned bx = blockIdx.x;
    if (bx < BSZ) {
        __shared__ float xs[GF];
        __shared__ float sg[GC];
        const int b = bx;
        const int tid = threadIdx.x;
        for (int f = tid; f < GF; f += 256) xs[f] = xg[b * GF + f];
        __syncthreads();
        if (tid < GC) {
            float a0 = 0.f, a1 = 0.f, a2 = 0.f, a3 = 0.f;
            #pragma unroll 4
            for (int f = 0; f < GF; f += 4) {
                a0 += xs[f + 0] * gw[(f + 0) * GC + tid];
                a1 += xs[f + 1] * gw[(f + 1) * GC + tid];
                a2 += xs[f + 2] * gw[(f + 2) * GC + tid];
                a3 += xs[f + 3] * gw[(f + 3) * GC + tid];
            }
            float z = (a0 + a1) + (a2 + a3) + gb[tid];
            sg[tid] = 1.f / (1.f + expf(-z));
        }
        __syncthreads();
        if (tid < NL) {
            const int l = tid;
            float p = 1.f;
            #pragma unroll
            for (int d = 0; d < 6; d++) {
                int node = l >> (6 - d);
                int idx  = (1 << d) - 1 + node;
                int bit  = (l >> (5 - d)) & 1;
                float g = sg[idx];
                p *= bit ? (1.f - g) : g;
            }
            g_leafp[b * NL + l] = p;
        }
    } else if (bx < BSZ + 512) {
        __shared__ float t[32][33];
        const int blk = bx - BSZ;                  // 0..511
        const int i0 = (blk & 15) * 32;            // [0, 512)
        const int b0 = (blk >> 4) * 32;            // [0, 1024)
        const int tx = threadIdx.x & 31, ty = threadIdx.x >> 5;
        for (int r = ty; r < 32; r += 8)
            t[r][tx] = xl[(size_t)(b0 + r) * IFT + i0 + tx];
        __syncthreads();
        for (int r = ty; r < 32; r += 8)
            g_xT[(size_t)(i0 + r) * BSZ + b0 + tx] = t[tx][r];
    } else if (bx < BSZ + 512 + 8192) {
        const int blk = bx - (BSZ + 512);          // 0..8191
        const int o = blk >> 4;                    // 0..511
        const int kseg = (blk & 15) << 11;         // 0,2048,...,30720
        const int e = kseg + threadIdx.x * 8;
        const float* src = pw + (size_t)o * KMAIN + e;
        float4 v0 = *reinterpret_cast<const float4*>(src);
        float4 v1 = *reinterpret_cast<const float4*>(src + 4);
        float v[8] = {v0.x, v0.y, v0.z, v0.w, v1.x, v1.y, v1.z, v1.w};
        pack8_store(v, reinterpret_cast<char*>(g_pwh + (size_t)o * KT2 + e));
    } else if (bx < BSZ + 512 + 8192 + 16) {
        const int blk = bx - (BSZ + 512 + 8192);   // 0..15
        const int e = blk * 2048 + threadIdx.x * 8;
        const int o = e >> 6, k = e & 63;
        const float* src = pb + (size_t)o * NL + k;
        float4 v0 = *reinterpret_cast<const float4*>(src);
        float4 v1 = *reinterpret_cast<const float4*>(src + 4);
        float v[8] = {v0.x, v0.y, v0.z, v0.w, v1.x, v1.y, v1.z, v1.w};
        pack8_store(v, reinterpret_cast<char*>(g_pwh + (size_t)o * KT2 + KMAIN + k));
    } else if (bx < BSZ + 512 + 8192 + 32) {
        // zero pad [32832, 32896) for every o row
        const int blk = bx - (BSZ + 512 + 8192 + 16);  // 0..15
        const int e = blk * 2048 + threadIdx.x * 8;    // over 512*64 = 32768
        const int o = e >> 6, k = e & 63;
        *reinterpret_cast<uint4*>(g_pwh + (size_t)o * KT2 + KTOT + k) =
            make_uint4(0u, 0u, 0u, 0u);
    } else {
        const int blk = bx - (BSZ + 512 + 8192 + 32);  // 0..511
        float4* dst = reinterpret_cast<float4*>(out) + blk * 256 + threadIdx.x;
        *dst = make_float4(0.f, 0.f, 0.f, 0.f);
    }
}

// ---------------------------------------------------------------------------
// Main GEMM: warp-specialized; K-chunk=128; 16 consumer + 4 producer warps
// ---------------------------------------------------------------------------
__device__ __forceinline__ void stage_B(uint32_t sb, int buf, int c, int pt,
                                        int n0) {
    uint32_t dst = sb + buf * SETSZ + OFF_B + pt * ROWB;
    const __half* src = g_pwh + (size_t)(n0 + pt) * KT2 + (size_t)c * 128;
    #pragma unroll
    for (int j = 0; j < 16; j++) CPA16(dst + j * 16, src + j * 8);
}

// xv for 64-unit u (0..513): feature, pb (=1), pad (=0)
__device__ __forceinline__ float xval(int u, int row) {
    if (u < 512) return g_xT[(size_t)u * BSZ + row];
    return (u == 512) ? 1.0f : 0.0f;
}

// 32(M) x 32(N) warp tile: 2 A ldsm + 2 B ldsm per ks (ks = 0..7)
__device__ __forceinline__ void ld_frags(uint32_t setb, int wm, int wn,
                                         int r, int kh, int ks,
                                         uint32_t (*av)[4], uint32_t (*bv)[2]) {
    const int kb = ks * 32 + kh * 16;     // byte offset within 256B row
    #pragma unroll
    for (int mt = 0; mt < 2; mt++)
        ldsm4(av[mt], setb + OFF_A + (32 * wm + 16 * mt + r) * ROWB + kb);
    #pragma unroll
    for (int g = 0; g < 2; g++) {
        uint32_t t[4];
        ldsm4(t, setb + OFF_B + (32 * wn + 16 * g + r) * ROWB + kb);
        bv[2*g][0] = t[0];   bv[2*g][1] = t[2];
        bv[2*g+1][0] = t[1]; bv[2*g+1][1] = t[3];
    }
}

#define MMA_BLOCK(cur)                                           \
    _Pragma("unroll")                                            \
    for (int mt = 0; mt < 2; mt++)                               \
        _Pragma("unroll")                                        \
        for (int nt = 0; nt < 4; nt++)                           \
            mma16816(acc[mt][nt], av[cur][mt], bv[cur][nt]);

__global__ void __launch_bounds__(NTHR, 1) hme_mma_kernel(float* __restrict__ out) {
    extern __shared__ char smem[];
    const uint32_t sb = smem_u32(smem);
    const int tid = threadIdx.x;
    const int lane = tid & 31, w = tid >> 5;
    const int n0 = blockIdx.x * TILE_N;
    const int m0 = blockIdx.y * TILE_M;
    const int s  = blockIdx.z;
    const int c0 = s * 64;
    const int nch = (s < 3) ? 64 : 65;     // 257 chunks total (incl. pad chunk)

    if (w < 16) {
        // ========= CONSUMERS: 32x32 warp tiles, 8 ks-steps per chunk =========
        const int wm = w >> 2, wn = w & 3;
        const int r = lane & 15, kh = lane >> 4;
        float acc[2][4][4];
        #pragma unroll
        for (int a = 0; a < 2; a++)
            #pragma unroll
            for (int b = 0; b < 4; b++)
                #pragma unroll
                for (int d = 0; d < 4; d++) acc[a][b][d] = 0.f;

        for (int it = 0; it < nch; ++it) {
            const int buf = it % NBUF;
            BAR_SYNC(BARF(buf));               // tiles[buf] full
            const uint32_t setb = sb + buf * SETSZ;

            uint32_t av[2][2][4], bv[2][4][2];
            ld_frags(setb, wm, wn, r, kh, 0, av[0], bv[0]);
            #pragma unroll
            for (int ks = 0; ks < 8; ks++) {
                const int cur = ks & 1;
                if (ks < 7)
                    ld_frags(setb, wm, wn, r, kh, ks + 1, av[cur ^ 1], bv[cur ^ 1]);
                else
                    BAR_ARRIVE(BARE(buf));     // after last ldsm: buffer free
                MMA_BLOCK(cur)
            }
        }

        // epilogue: accumulate into out via red.global.add
        #pragma unroll
        for (int mt = 0; mt < 2; mt++) {
            int m = m0 + 32 * wm + 16 * mt + (lane >> 2);
            #pragma unroll
            for (int nt = 0; nt < 4; nt++) {
                int n = n0 + 32 * wn + 8 * nt + (lane & 3) * 2;
                float* p0 = out + (size_t)m * OFT + n;
                float* p1 = out + (size_t)(m + 8) * OFT + n;
                atomicAdd(p0,     acc[mt][nt][0]);
                atomicAdd(p0 + 1, acc[mt][nt][1]);
                atomicAdd(p1,     acc[mt][nt][2]);
                atomicAdd(p1 + 1, acc[mt][nt][3]);
            }
        }
    } else {
        // ========= PRODUCERS: fp16 B via cp.async (1 chunk ahead) + A gen ====
        const int pt = tid - 512;              // 0..127: one tile row per thread
        float pr[64];                          // leaf probs p[m0+pt][0..63]
        {
            const float4* pp = reinterpret_cast<const float4*>(
                g_leafp + (size_t)(m0 + pt) * NL);
            #pragma unroll
            for (int j = 0; j < 16; j++) {
                float4 v = pp[j];
                pr[4*j] = v.x; pr[4*j+1] = v.y; pr[4*j+2] = v.z; pr[4*j+3] = v.w;
            }
        }
        const int row = m0 + pt;

        stage_B(sb, 0, c0, pt, n0);            // buffers start empty
        CPCOMMIT();
        float xv0n = xval(2 * c0,     row);
        float xv1n = xval(2 * c0 + 1, row);

        for (int it = 0; it < nch; ++it) {
            const int c = c0 + it;
            const int buf = it % NBUF;

            if (it + 1 < nch) {
                const int nb = (it + 1) % NBUF;
                if (it + 1 >= NBUF) BAR_SYNC(BARE(nb)); // buffer nb fully freed
                stage_B(sb, nb, c + 1, pt, n0);
                CPCOMMIT();
                CPWAIT1();                     // B[it] landed (B[it+1] in flight)
            } else {
                CPWAIT0();                     // last chunk: drain everything
            }

            const float xv0 = xv0n, xv1 = xv1n;
            if (it + 1 < nch) {
                xv0n = xval(2 * (c + 1),     row);
                xv1n = xval(2 * (c + 1) + 1, row);
            }

            // A tile row (256B): [xv0 * p[0..63] | xv1 * p[0..63]]
            char* At = smem + buf * SETSZ + OFF_A + pt * ROWB;
            #pragma unroll
            for (int q = 0; q < 8; q++) {
                float v[8];
                #pragma unroll
                for (int j = 0; j < 8; j++) v[j] = xv0 * pr[q * 8 + j];
                pack8_store(v, At + q * 16);
            }
            #pragma unroll
            for (int q = 0; q < 8; q++) {
                float v[8];
                #pragma unroll
                for (int j = 0; j < 8; j++) v[j] = xv1 * pr[q * 8 + j];
                pack8_store(v, At + 128 + q * 16);
            }

            BAR_ARRIVE(BARF(buf));             // tiles[buf] full
        }
    }
}

// ---------------------------------------------------------------------------
extern "C" void kernel_launch(void* const* d_in, const int* in_sizes, int n_in,
                              void* d_out, int out_size) {
    const float* xg = (const float*)d_in[0];  // x_gating [1024,512]
    const float* xl = (const float*)d_in[1];  // x_leaf   [1024,512]
    const float* gw = (const float*)d_in[2];  // [512,63]
    const float* gb = (const float*)d_in[3];  // [63]
    const float* pw = (const float*)d_in[4];  // [512,512,64]
    const float* pb = (const float*)d_in[5];  // [512,64]
    float* out = (float*)d_out;               // [1024,512] f32

    cudaFuncSetAttribute(hme_mma_kernel,
                         cudaFuncAttributeMaxDynamicSharedMemorySize, SMEM_SZ);

    prep_kernel<<<BSZ + 512 + 8192 + 32 + 512, 256>>>(xg, gw, gb, xl, pw, pb, out);

    dim3 grid(OFT / TILE_N, BSZ / TILE_M, KSPLIT);   // (4, 8, 4) = 128 CTAs
    hme_mma_kernel<<<grid, NTHR, SMEM_SZ>>>(out);
}

// round 14
// speedup vs baseline: 1.1078x; 1.1078x over previous
#include <cuda_runtime.h>
#include <cuda_fp16.h>
#include <cstdint>

#define BSZ 1024
#define GF 512
#define IFT 512
#define OFT 512
#define NL 64
#define GC 63
#define KMAIN (IFT * NL)          // 32768
#define KTOT (KMAIN + NL)         // 32832
#define KT2   32896               // padded to 257 chunks of 128
#define NCHUNK 257
#define NTILE 32                  // 8 M-tiles x 4 N-tiles (128x128)
#define WTOT (NTILE * NCHUNK)     // 8224 work units
#define NCTA 148
#define TILE_M 128
#define TILE_N 128
#define NTHR 640                  // 16 consumer warps + 4 producer warps
#define NBUF 3

// ---------------------------------------------------------------------------
// static device scratch
// ---------------------------------------------------------------------------
__device__ __align__(256) float  g_leafp[BSZ * NL];                  // 256KB
__device__ __align__(256) float  g_xT[IFT * BSZ];                    // 2MB
__device__ __align__(256) __half g_pwh[(size_t)OFT * KT2];           // 33.7MB fp16 B

// ---------------------------------------------------------------------------
// smem layout: 3 fp16 tile-sets (A|B), 256B rows (K-chunk = 128 fp16)
// ---------------------------------------------------------------------------
#define ROWB 272                    // fp16 tile row stride (128*2 + 16 pad)
#define TILEB (128 * ROWB)          // 34816
#define SETSZ (2 * TILEB)           // A | B = 69632
#define OFF_A 0
#define OFF_B TILEB
#define SMEM_SZ (NBUF * SETSZ)      // 208896

// named barriers: full[0..2] = 1..3, empty[0..2] = 4..6
#define BARF(b) (1 + (b))
#define BARE(b) (4 + (b))
#define BAR_SYNC(id)   asm volatile("bar.sync %0, %1;"   :: "r"(id), "r"(NTHR) : "memory")
#define BAR_ARRIVE(id) asm volatile("bar.arrive %0, %1;" :: "r"(id), "r"(NTHR) : "memory")

// ---------------------------------------------------------------------------
// PTX helpers (base sm_103 target only — no 'a'-gated instructions)
// ---------------------------------------------------------------------------
__device__ __forceinline__ uint32_t smem_u32(const void* p) {
    uint32_t a;
    asm("{ .reg .u64 t; cvta.to.shared.u64 t, %1; cvt.u32.u64 %0, t; }" : "=r"(a) : "l"(p));
    return a;
}
#define CPA16(dst, src) \
    asm volatile("cp.async.cg.shared.global [%0], [%1], 16;" :: "r"(dst), "l"(src) : "memory")
#define CPCOMMIT() asm volatile("cp.async.commit_group;" ::: "memory")
#define CPWAIT1()  asm volatile("cp.async.wait_group 1;" ::: "memory")
#define CPWAIT0()  asm volatile("cp.async.wait_group 0;" ::: "memory")

__device__ __forceinline__ void ldsm4(uint32_t (&r)[4], uint32_t a) {
    asm volatile("ldmatrix.sync.aligned.m8n8.x4.shared.b16 {%0,%1,%2,%3}, [%4];"
        : "=r"(r[0]), "=r"(r[1]), "=r"(r[2]), "=r"(r[3]) : "r"(a));
}
__device__ __forceinline__ void mma16816(float* d, const uint32_t* a, const uint32_t* b) {
    asm volatile("mma.sync.aligned.m16n8k16.row.col.f32.f16.f16.f32 "
        "{%0,%1,%2,%3}, {%4,%5,%6,%7}, {%8,%9}, {%0,%1,%2,%3};"
        : "+f"(d[0]), "+f"(d[1]), "+f"(d[2]), "+f"(d[3])
        : "r"(a[0]), "r"(a[1]), "r"(a[2]), "r"(a[3]), "r"(b[0]), "r"(b[1]));
}
__device__ __forceinline__ uint32_t hbits2(__half2 h) {
    return *reinterpret_cast<uint32_t*>(&h);
}
__device__ __forceinline__ void pack8_store(const float* v, char* dst) {
    __half2 h0 = __floats2half2_rn(v[0], v[1]);
    __half2 h1 = __floats2half2_rn(v[2], v[3]);
    __half2 h2 = __floats2half2_rn(v[4], v[5]);
    __half2 h3 = __floats2half2_rn(v[6], v[7]);
    *reinterpret_cast<uint4*>(dst) = make_uint4(hbits2(h0), hbits2(h1), hbits2(h2), hbits2(h3));
}

// tile id -> coordinates
__device__ __forceinline__ int tile_m0(int t) { return (t >> 2) * TILE_M; }
__device__ __forceinline__ int tile_n0(int t) { return (t & 3) * TILE_N; }

// ---------------------------------------------------------------------------
// Kernel 1 (fused prep) — unchanged from R13
// ---------------------------------------------------------------------------
__global__ void prep_kernel(const float* __restrict__ xg,
                            const float* __restrict__ gw,
                            const float* __restrict__ gb,
                            const float* __restrict__ xl,
                            const float* __restrict__ pw,
                            const float* __restrict__ pb,
                            float* __restrict__ out) {
    const unsigned bx = blockIdx.x;
    if (bx < BSZ) {
        __shared__ float xs[GF];
        __shared__ float sg[GC];
        const int b = bx;
        const int tid = threadIdx.x;
        for (int f = tid; f < GF; f += 256) xs[f] = xg[b * GF + f];
        __syncthreads();
        if (tid < GC) {
            float a0 = 0.f, a1 = 0.f, a2 = 0.f, a3 = 0.f;
            #pragma unroll 4
            for (int f = 0; f < GF; f += 4) {
                a0 += xs[f + 0] * gw[(f + 0) * GC + tid];
                a1 += xs[f + 1] * gw[(f + 1) * GC + tid];
                a2 += xs[f + 2] * gw[(f + 2) * GC + tid];
                a3 += xs[f + 3] * gw[(f + 3) * GC + tid];
            }
            float z = (a0 + a1) + (a2 + a3) + gb[tid];
            sg[tid] = 1.f / (1.f + expf(-z));
        }
        __syncthreads();
        if (tid < NL) {
            const int l = tid;
            float p = 1.f;
            #pragma unroll
            for (int d = 0; d < 6; d++) {
                int node = l >> (6 - d);
                int idx  = (1 << d) - 1 + node;
                int bit  = (l >> (5 - d)) & 1;
                float g = sg[idx];
                p *= bit ? (1.f - g) : g;
            }
            g_leafp[b * NL + l] = p;
        }
    } else if (bx < BSZ + 512) {
        __shared__ float t[32][33];
        const int blk = bx - BSZ;                  // 0..511
        const int i0 = (blk & 15) * 32;            // [0, 512)
        const int b0 = (blk >> 4) * 32;            // [0, 1024)
        const int tx = threadIdx.x & 31, ty = threadIdx.x >> 5;
        for (int r = ty; r < 32; r += 8)
            t[r][tx] = xl[(size_t)(b0 + r) * IFT + i0 + tx];
        __syncthreads();
        for (int r = ty; r < 32; r += 8)
            g_xT[(size_t)(i0 + r) * BSZ + b0 + tx] = t[tx][r];
    } else if (bx < BSZ + 512 + 8192) {
        const int blk = bx - (BSZ + 512);          // 0..8191
        const int o = blk >> 4;                    // 0..511
        const int kseg = (blk & 15) << 11;         // 0,2048,...,30720
        const int e = kseg + threadIdx.x * 8;
        const float* src = pw + (size_t)o * KMAIN + e;
        float4 v0 = *reinterpret_cast<const float4*>(src);
        float4 v1 = *reinterpret_cast<const float4*>(src + 4);
        float v[8] = {v0.x, v0.y, v0.z, v0.w, v1.x, v1.y, v1.z, v1.w};
        pack8_store(v, reinterpret_cast<char*>(g_pwh + (size_t)o * KT2 + e));
    } else if (bx < BSZ + 512 + 8192 + 16) {
        const int blk = bx - (BSZ + 512 + 8192);   // 0..15
        const int e = blk * 2048 + threadIdx.x * 8;
        const int o = e >> 6, k = e & 63;
        const float* src = pb + (size_t)o * NL + k;
        float4 v0 = *reinterpret_cast<const float4*>(src);
        float4 v1 = *reinterpret_cast<const float4*>(src + 4);
        float v[8] = {v0.x, v0.y, v0.z, v0.w, v1.x, v1.y, v1.z, v1.w};
        pack8_store(v, reinterpret_cast<char*>(g_pwh + (size_t)o * KT2 + KMAIN + k));
    } else if (bx < BSZ + 512 + 8192 + 32) {
        const int blk = bx - (BSZ + 512 + 8192 + 16);  // 0..15
        const int e = blk * 2048 + threadIdx.x * 8;    // over 512*64 = 32768
        const int o = e >> 6, k = e & 63;
        *reinterpret_cast<uint4*>(g_pwh + (size_t)o * KT2 + KTOT + k) =
            make_uint4(0u, 0u, 0u, 0u);
    } else {
        const int blk = bx - (BSZ + 512 + 8192 + 32);  // 0..511
        float4* dst = reinterpret_cast<float4*>(out) + blk * 256 + threadIdx.x;
        *dst = make_float4(0.f, 0.f, 0.f, 0.f);
    }
}

// ---------------------------------------------------------------------------
// Main GEMM: 148 persistent CTAs, flat (tile, chunk) work range per CTA
// ---------------------------------------------------------------------------
__device__ __forceinline__ void stage_B(uint32_t sb, int buf, int t, int c,
                                        int pt) {
    uint32_t dst = sb + buf * SETSZ + OFF_B + pt * ROWB;
    const __half* src = g_pwh + (size_t)(tile_n0(t) + pt) * KT2 + (size_t)c * 128;
    #pragma unroll
    for (int j = 0; j < 16; j++) CPA16(dst + j * 16, src + j * 8);
}

// xv for 64-unit u (0..513): feature, pb (=1), pad (=0)
__device__ __forceinline__ float xval(int u, int row) {
    if (u < 512) return g_xT[(size_t)u * BSZ + row];
    return (u == 512) ? 1.0f : 0.0f;
}

// 32(M) x 32(N) warp tile: 2 A ldsm + 2 B ldsm per ks (ks = 0..7)
__device__ __forceinline__ void ld_frags(uint32_t setb, int wm, int wn,
                                         int r, int kh, int ks,
                                         uint32_t (*av)[4], uint32_t (*bv)[2]) {
    const int kb = ks * 32 + kh * 16;     // byte offset within 256B row
    #pragma unroll
    for (int mt = 0; mt < 2; mt++)
        ldsm4(av[mt], setb + OFF_A + (32 * wm + 16 * mt + r) * ROWB + kb);
    #pragma unroll
    for (int g = 0; g < 2; g++) {
        uint32_t t[4];
        ldsm4(t, setb + OFF_B + (32 * wn + 16 * g + r) * ROWB + kb);
        bv[2*g][0] = t[0];   bv[2*g][1] = t[2];
        bv[2*g+1][0] = t[1]; bv[2*g+1][1] = t[3];
    }
}

#define MMA_BLOCK(cur)                                           \
    _Pragma("unroll")                                            \
    for (int mt = 0; mt < 2; mt++)                               \
        _Pragma("unroll")                                        \
        for (int nt = 0; nt < 4; nt++)                           \
            mma16816(acc[mt][nt], av[cur][mt], bv[cur][nt]);

__global__ void __launch_bounds__(NTHR, 1) hme_mma_kernel(float* __restrict__ out) {
    extern __shared__ char smem[];
    const uint32_t sb = smem_u32(smem);
    const int tid = threadIdx.x;
    const int lane = tid & 31, w = tid >> 5;
    const int j = blockIdx.x;

    // flat work range [gs, ge) over (tile, chunk) pairs
    const int gs = (WTOT * j) / NCTA;
    const int ge = (WTOT * (j + 1)) / NCTA;
    const int nit = ge - gs;                       // 55 or 56

    int t0 = gs / NCHUNK;
    int cc0 = gs - t0 * NCHUNK;

    if (w < 16) {
        // ========= CONSUMERS: 32x32 warp tiles; flush acc on tile change =====
        const int wm = w >> 2, wn = w & 3;
        const int r = lane & 15, kh = lane >> 4;
        float acc[2][4][4];
        #pragma unroll
        for (int a = 0; a < 2; a++)
            #pragma unroll
            for (int b = 0; b < 4; b++)
                #pragma unroll
                for (int d = 0; d < 4; d++) acc[a][b][d] = 0.f;

        int t = t0, c = cc0, tflush = t0;
        for (int it = 0; it < nit; ++it) {
            if (t != tflush) {
                // flush accumulators of finished tile
                const int m0 = tile_m0(tflush), n0 = tile_n0(tflush);
                #pragma unroll
                for (int mt = 0; mt < 2; mt++) {
                    int m = m0 + 32 * wm + 16 * mt + (lane >> 2);
                    #pragma unroll
                    for (int nt = 0; nt < 4; nt++) {
                        int n = n0 + 32 * wn + 8 * nt + (lane & 3) * 2;
                        float* p0 = out + (size_t)m * OFT + n;
                        float* p1 = out + (size_t)(m + 8) * OFT + n;
                        atomicAdd(p0,     acc[mt][nt][0]);
                        atomicAdd(p0 + 1, acc[mt][nt][1]);
                        atomicAdd(p1,     acc[mt][nt][2]);
                        atomicAdd(p1 + 1, acc[mt][nt][3]);
                        acc[mt][nt][0] = acc[mt][nt][1] = 0.f;
                        acc[mt][nt][2] = acc[mt][nt][3] = 0.f;
                    }
                }
                tflush = t;
            }

            const int buf = it % NBUF;
            BAR_SYNC(BARF(buf));               // tiles[buf] full
            const uint32_t setb = sb + buf * SETSZ;

            uint32_t av[2][2][4], bv[2][4][2];
            ld_frags(setb, wm, wn, r, kh, 0, av[0], bv[0]);
            #pragma unroll
            for (int ks = 0; ks < 8; ks++) {
                const int cur = ks & 1;
                if (ks < 7)
                    ld_frags(setb, wm, wn, r, kh, ks + 1, av[cur ^ 1], bv[cur ^ 1]);
                else
                    BAR_ARRIVE(BARE(buf));     // after last ldsm: buffer free
                MMA_BLOCK(cur)
            }

            if (++c == NCHUNK) { c = 0; ++t; }
        }

        // final flush
        {
            const int m0 = tile_m0(tflush), n0 = tile_n0(tflush);
            #pragma unroll
            for (int mt = 0; mt < 2; mt++) {
                int m = m0 + 32 * wm + 16 * mt + (lane >> 2);
                #pragma unroll
                for (int nt = 0; nt < 4; nt++) {
                    int n = n0 + 32 * wn + 8 * nt + (lane & 3) * 2;
                    float* p0 = out + (size_t)m * OFT + n;
                    float* p1 = out + (size_t)(m + 8) * OFT + n;
                    atomicAdd(p0,     acc[mt][nt][0]);
                    atomicAdd(p0 + 1, acc[mt][nt][1]);
                    atomicAdd(p1,     acc[mt][nt][2]);
                    atomicAdd(p1 + 1, acc[mt][nt][3]);
                }
            }
        }
    } else {
        // ========= PRODUCERS: fp16 B via cp.async (1 ahead) + A gen ==========
        const int pt = tid - 512;              // 0..127: one tile row per thread
        float pr[64];                          // leaf probs for current tile
        int t = t0, c = cc0;
        int tpr = t0;                          // tile whose pr[] is loaded
        {
            const float4* pp = reinterpret_cast<const float4*>(
                g_leafp + (size_t)(tile_m0(t0) + pt) * NL);
            #pragma unroll
            for (int jj = 0; jj < 16; jj++) {
                float4 v = pp[jj];
                pr[4*jj] = v.x; pr[4*jj+1] = v.y; pr[4*jj+2] = v.z; pr[4*jj+3] = v.w;
            }
        }

        stage_B(sb, 0, t0, cc0, pt);           // buffers start empty
        CPCOMMIT();
        float xv0n = xval(2 * cc0,     tile_m0(t0) + pt);
        float xv1n = xval(2 * cc0 + 1, tile_m0(t0) + pt);

        for (int it = 0; it < nit; ++it) {
            // next work unit coords
            int tn = t, cn = c + 1;
            if (cn == NCHUNK) { cn = 0; ++tn; }

            if (it + 1 < nit) {
                const int nb = (it + 1) % NBUF;
                if (it + 1 >= NBUF) BAR_SYNC(BARE(nb)); // buffer nb fully freed
                stage_B(sb, nb, tn, cn, pt);
                CPCOMMIT();
                CPWAIT1();                     // B[it] landed (B[it+1] in flight)
            } else {
                CPWAIT0();                     // last chunk: drain everything
            }

            const float xv0 = xv0n, xv1 = xv1n;
            if (it + 1 < nit) {
                const int rown = tile_m0(tn) + pt;
                xv0n = xval(2 * cn,     rown);
                xv1n = xval(2 * cn + 1, rown);
            }

            // reload pr[] when tile changed (new m0)
            if (t != tpr) {
                const float4* pp = reinterpret_cast<const float4*>(
                    g_leafp + (size_t)(tile_m0(t) + pt) * NL);
                #pragma unroll
                for (int jj = 0; jj < 16; jj++) {
                    float4 v = pp[jj];
                    pr[4*jj] = v.x; pr[4*jj+1] = v.y;
                    pr[4*jj+2] = v.z; pr[4*jj+3] = v.w;
                }
                tpr = t;
            }

            const int buf = it % NBUF;
            char* At = smem + buf * SETSZ + OFF_A + pt * ROWB;
            #pragma unroll
            for (int q = 0; q < 8; q++) {
                float v[8];
                #pragma unroll
                for (int jj = 0; jj < 8; jj++) v[jj] = xv0 * pr[q * 8 + jj];
                pack8_store(v, At + q * 16);
            }
            #pragma unroll
            for (int q = 0; q < 8; q++) {
                float v[8];
                #pragma unroll
                for (int jj = 0; jj < 8; jj++) v[jj] = xv1 * pr[q * 8 + jj];
                pack8_store(v, At + 128 + q * 16);
            }

            BAR_ARRIVE(BARF(buf));             // tiles[buf] full

            t = tn; c = cn;
        }
    }
}

// ---------------------------------------------------------------------------
extern "C" void kernel_launch(void* const* d_in, const int* in_sizes, int n_in,
                              void* d_out, int out_size) {
    const float* xg = (const float*)d_in[0];  // x_gating [1024,512]
    const float* xl = (const float*)d_in[1];  // x_leaf   [1024,512]
    const float* gw = (const float*)d_in[2];  // [512,63]
    const float* gb = (const float*)d_in[3];  // [63]
    const float* pw = (const float*)d_in[4];  // [512,512,64]
    const float* pb = (const float*)d_in[5];  // [512,64]
    float* out = (float*)d_out;               // [1024,512] f32

    cudaFuncSetAttribute(hme_mma_kernel,
                         cudaFuncAttributeMaxDynamicSharedMemorySize, SMEM_SZ);

    prep_kernel<<<BSZ + 512 + 8192 + 32 + 512, 256>>>(xg, gw, gb, xl, pw, pb, out);

    hme_mma_kernel<<<NCTA, NTHR, SMEM_SZ>>>(out);
}